// round 1
// baseline (speedup 1.0000x reference)
#include <cuda_runtime.h>
#include <math.h>

#define B_  32
#define NH  778
#define NO  3000
#define Z_  64
#define NPRIOR 204
#define TILE 256

// Accumulators:
// 0: recon MSE sum   1: kld sum   2: penetr sum   3: n_pts
// 4: contact sum     5: consist   6: loss_o sum   7: loss_h sum
__device__ double g_acc[8];
__device__ unsigned char g_mask[NH];

__constant__ int c_prior[NPRIOR] = {
  // _F1
  697,698,699,700,712,713,714,715,737,738,739,740,741,743,744,745,
  746,748,749,750,753,754,755,756,757,758,759,760,761,762,763,764,
  765,766,767,768,
  // _F2
  46,47,48,49,164,165,166,167,194,195,223,237,238,280,281,298,
  301,317,320,323,324,325,326,327,328,329,330,331,332,333,340,341,
  342,343,344,345,346,347,348,349,350,351,352,353,354,355,
  // _F3
  356,357,358,359,375,376,386,387,396,397,402,403,413,429,433,434,
  435,436,437,438,439,440,441,442,443,444,452,453,454,455,456,459,
  460,461,462,463,464,465,466,467,
  // _F4
  468,469,470,471,484,485,486,496,497,506,507,513,514,524,545,546,
  547,548,549,550,551,552,553,555,563,564,565,566,567,570,572,573,
  574,575,576,577,578,
  // _F5
  580,581,582,583,600,601,602,614,615,624,625,630,631,641,663,664,
  665,666,667,668,670,672,680,681,682,683,684,686,687,688,689,690,
  691,692,693,694,695,
  // _F0
  73,96,98,99,772,774,775,777
};

__global__ void k_init() {
    int t = threadIdx.x;
    if (t < 8) g_acc[t] = 0.0;
    for (int i = t; i < NH; i += blockDim.x) g_mask[i] = 0;
    __syncthreads();
    if (t < NPRIOR) g_mask[c_prior[t]] = 1;
}

__device__ __forceinline__ float warp_sum(float v) {
#pragma unroll
    for (int o = 16; o > 0; o >>= 1) v += __shfl_down_sync(0xffffffffu, v, o);
    return v;
}

__device__ __forceinline__ float sgnf(float x) {
    return (x > 0.f) ? 1.f : ((x < 0.f) ? -1.f : 0.f);
}

// One thread per obj point. Scans recon (with prior-subset min) and gt tiles.
__global__ void __launch_bounds__(256) k_obj(
    const float* __restrict__ recon, const float* __restrict__ gt,
    const float* __restrict__ recon_n, const float* __restrict__ gt_n,
    const float* __restrict__ obj)
{
    const int b = blockIdx.y;
    const int j = blockIdx.x * blockDim.x + threadIdx.x;
    const bool active = (j < NO);

    float ox = 0.f, oy = 0.f, oz = 0.f;
    if (active) {
        const float* op = obj + ((size_t)b * NO + j) * 3;
        ox = op[0]; oy = op[1]; oz = op[2];
    }

    __shared__ float s_pts[TILE * 3];
    __shared__ unsigned char s_flag[TILE];

    // ---- recon pass (plus prior subset) ----
    float best_r = 3.4e38f, best_p = 3.4e38f;
    int idx_r = 0;
    {
        const float* base = recon + (size_t)b * NH * 3;
        for (int t0 = 0; t0 < NH; t0 += TILE) {
            const int cnt = min(TILE, NH - t0);
            __syncthreads();
            for (int k = threadIdx.x; k < cnt * 3; k += blockDim.x)
                s_pts[k] = base[t0 * 3 + k];
            for (int k = threadIdx.x; k < cnt; k += blockDim.x)
                s_flag[k] = g_mask[t0 + k];
            __syncthreads();
            if (active) {
#pragma unroll 4
                for (int k = 0; k < cnt; k++) {
                    float dx = ox - s_pts[3 * k];
                    float dy = oy - s_pts[3 * k + 1];
                    float dz = oz - s_pts[3 * k + 2];
                    float d2 = dx * dx + dy * dy + dz * dz;
                    if (d2 < best_r) { best_r = d2; idx_r = t0 + k; }
                    if (s_flag[k] && d2 < best_p) best_p = d2;
                }
            }
        }
    }

    // ---- gt pass ----
    float best_g = 3.4e38f;
    int idx_g = 0;
    {
        const float* base = gt + (size_t)b * NH * 3;
        for (int t0 = 0; t0 < NH; t0 += TILE) {
            const int cnt = min(TILE, NH - t0);
            __syncthreads();
            for (int k = threadIdx.x; k < cnt * 3; k += blockDim.x)
                s_pts[k] = base[t0 * 3 + k];
            __syncthreads();
            if (active) {
#pragma unroll 4
                for (int k = 0; k < cnt; k++) {
                    float dx = ox - s_pts[3 * k];
                    float dy = oy - s_pts[3 * k + 1];
                    float dz = oz - s_pts[3 * k + 2];
                    float d2 = dx * dx + dy * dy + dz * dz;
                    if (d2 < best_g) { best_g = d2; idx_g = t0 + k; }
                }
            }
        }
    }

    float penetr_c = 0.f, npts_c = 0.f, contact_c = 0.f, consist_c = 0.f, losso_c = 0.f;
    if (active) {
        // recon nearest: recompute exact diff + signed distance
        const float* rp = recon   + ((size_t)b * NH + idx_r) * 3;
        const float* rn = recon_n + ((size_t)b * NH + idx_r) * 3;
        float dxr = ox - rp[0], dyr = oy - rp[1], dzr = oz - rp[2];
        float d2r = dxr * dxr + dyr * dyr + dzr * dzr;
        float dotr = rn[0] * dxr + rn[1] * dyr + rn[2] * dzr;
        float o2h = sqrtf(d2r) * sgnf(dotr);
        // interior = dot(nn_hand - obj, nn_normal) > 0  ==  -dotr > 0
        bool interior = (-dotr) > 0.f;

        const float* gp = gt   + ((size_t)b * NH + idx_g) * 3;
        const float* gn = gt_n + ((size_t)b * NH + idx_g) * 3;
        float dxg = ox - gp[0], dyg = oy - gp[1], dzg = oz - gp[2];
        float d2g = dxg * dxg + dyg * dyg + dzg * dzg;
        float dotg = gn[0] * dxg + gn[1] * dyg + gn[2] * dzg;
        float o2h_gt = sqrtf(d2g) * sgnf(dotg);

        bool cmap  = sqrtf(best_g) < 0.005f;
        bool rcmap = sqrtf(best_r) < 0.005f;

        penetr_c  = interior ? best_r : 0.f;
        npts_c    = cmap ? 1.f : 0.f;
        contact_c = cmap ? best_p : 0.f;
        consist_c = (cmap && rcmap) ? 1.f : 0.f;

        bool w_dist = (o2h_gt < 0.01f) && (o2h_gt > -0.005f);
        float w = (o2h < 0.f) ? 1.5f : (w_dist ? 1.0f : 0.1f);
        losso_c = fabsf(o2h - o2h_gt) * w;
    }

    // block reduce 5 values
    __shared__ float red[8][5];
    float vals[5] = { penetr_c, npts_c, contact_c, consist_c, losso_c };
    int lane = threadIdx.x & 31, warp = threadIdx.x >> 5;
#pragma unroll
    for (int q = 0; q < 5; q++) {
        float v = warp_sum(vals[q]);
        if (lane == 0) red[warp][q] = v;
    }
    __syncthreads();
    if (threadIdx.x == 0) {
#pragma unroll
        for (int q = 0; q < 5; q++) {
            float s = 0.f;
            for (int wi = 0; wi < 8; wi++) s += red[wi][q];
            atomicAdd(&g_acc[2 + q], (double)s);
        }
    }
}

// One thread per hand point; scans obj tiles once, keeping mins for both
// its recon point and its gt point.
__global__ void __launch_bounds__(256) k_hand(
    const float* __restrict__ recon, const float* __restrict__ gt,
    const float* __restrict__ obj, const float* __restrict__ vw)
{
    const int b = blockIdx.y;
    const int i = blockIdx.x * blockDim.x + threadIdx.x;
    const bool active = (i < NH);

    float rx = 0.f, ry = 0.f, rz = 0.f, gx = 0.f, gy = 0.f, gz = 0.f;
    if (active) {
        const float* rp = recon + ((size_t)b * NH + i) * 3;
        const float* gp = gt    + ((size_t)b * NH + i) * 3;
        rx = rp[0]; ry = rp[1]; rz = rp[2];
        gx = gp[0]; gy = gp[1]; gz = gp[2];
    }

    __shared__ float s_pts[TILE * 3];
    float best_r = 3.4e38f, best_g = 3.4e38f;
    const float* base = obj + (size_t)b * NO * 3;

    for (int t0 = 0; t0 < NO; t0 += TILE) {
        const int cnt = min(TILE, NO - t0);
        __syncthreads();
        for (int k = threadIdx.x; k < cnt * 3; k += blockDim.x)
            s_pts[k] = base[t0 * 3 + k];
        __syncthreads();
        if (active) {
#pragma unroll 4
            for (int k = 0; k < cnt; k++) {
                float px = s_pts[3 * k], py = s_pts[3 * k + 1], pz = s_pts[3 * k + 2];
                float dx = rx - px, dy = ry - py, dz = rz - pz;
                float d2 = dx * dx + dy * dy + dz * dz;
                best_r = fminf(best_r, d2);
                dx = gx - px; dy = gy - py; dz = gz - pz;
                d2 = dx * dx + dy * dy + dz * dz;
                best_g = fminf(best_g, d2);
            }
        }
    }

    float c = 0.f;
    if (active) {
        float h2o    = sqrtf(best_r);
        float h2o_gt = sqrtf(best_g);
        float vw2 = powf(vw[i], 0.4f);
        c = fabsf(h2o - h2o_gt) * vw2;
    }

    __shared__ float red[8];
    int lane = threadIdx.x & 31, warp = threadIdx.x >> 5;
    float v = warp_sum(c);
    if (lane == 0) red[warp] = v;
    __syncthreads();
    if (threadIdx.x == 0) {
        float s = 0.f;
        for (int wi = 0; wi < 8; wi++) s += red[wi];
        atomicAdd(&g_acc[7], (double)s);
    }
}

__global__ void k_small(
    const float* __restrict__ recon, const float* __restrict__ gt,
    const float* __restrict__ mean, const float* __restrict__ logv)
{
    const int NREC = B_ * NH * 3;
    const int NKLD = B_ * Z_;
    float s_rec = 0.f, s_kld = 0.f;
    int stride = gridDim.x * blockDim.x;
    for (int i = blockIdx.x * blockDim.x + threadIdx.x; i < NREC; i += stride) {
        float d = recon[i] - gt[i];
        s_rec += d * d;
    }
    for (int i = blockIdx.x * blockDim.x + threadIdx.x; i < NKLD; i += stride) {
        float m = mean[i], lv = logv[i];
        s_kld += 1.f + lv - m * m - expf(lv);
    }

    __shared__ float red[8][2];
    int lane = threadIdx.x & 31, warp = threadIdx.x >> 5;
    float v0 = warp_sum(s_rec), v1 = warp_sum(s_kld);
    if (lane == 0) { red[warp][0] = v0; red[warp][1] = v1; }
    __syncthreads();
    if (threadIdx.x == 0) {
        float a = 0.f, b = 0.f;
        for (int wi = 0; wi < 8; wi++) { a += red[wi][0]; b += red[wi][1]; }
        atomicAdd(&g_acc[0], (double)a);
        atomicAdd(&g_acc[1], (double)b);
    }
}

__global__ void k_final(float* out) {
    const double KLC = 0.005;
    double recon_loss = g_acc[0] / B_;
    double kld        = -0.5 * g_acc[1] / B_ * 10.0;
    double penetr     = 100.0 * g_acc[2] / B_;
    double npts       = g_acc[3];
    double contact    = 3000.0 * ((npts > 0.0) ? (g_acc[4] / (B_ * npts)) : 0.0);
    double consist    = -5.0 * g_acc[5] / (npts + 0.0001);
    double loss_o     = 30.0 * (1.0 - KLC) * g_acc[6] / ((double)B_ * NO);
    double loss_h     = 35.0 * (1.0 - KLC) * g_acc[7] / ((double)B_ * NH);
    double total = 1.0 * recon_loss + 0.1 * kld + 1000.0 * penetr
                 + 10.0 * contact + 10.0 * consist + (loss_h + loss_o);
    out[0] = (float)total;
}

extern "C" void kernel_launch(void* const* d_in, const int* in_sizes, int n_in,
                              void* d_out, int out_size) {
    const float* recon   = (const float*)d_in[0];
    const float* gt      = (const float*)d_in[1];
    const float* recon_n = (const float*)d_in[2];
    const float* gt_n    = (const float*)d_in[3];
    const float* obj     = (const float*)d_in[4];
    const float* mean    = (const float*)d_in[5];
    const float* logv    = (const float*)d_in[6];
    const float* vw      = (const float*)d_in[7];
    float* out = (float*)d_out;

    k_init<<<1, 1024>>>();
    k_obj<<<dim3((NO + 255) / 256, B_), 256>>>(recon, gt, recon_n, gt_n, obj);
    k_hand<<<dim3((NH + 255) / 256, B_), 256>>>(recon, gt, obj, vw);
    k_small<<<64, 256>>>(recon, gt, mean, logv);
    k_final<<<1, 1>>>(out);
}